// round 16
// baseline (speedup 1.0000x reference)
#include <cuda_runtime.h>
#include <cuda_bf16.h>
#include <cstdint>
#include <math.h>

// dims: N=64, C=64, T=512, V=25, S=3, I=16
// ---------------- device scratch (no cudaMalloc allowed) ----------------
__device__ float g_Apart[1536u * 1024u];      // [(n*3+s)*8+seg][v32*32]
__device__ float g_Aeff[192 * 625];           // [n*3+s][v][w]
__device__ __nv_bfloat16 g_Wd2h[192 * 72];    // [k=s*64+c][o pad72] bf16 hi
__device__ __nv_bfloat16 g_Wd2l[192 * 72];    // bf16 lo
__device__ __nv_bfloat16 g_Wt9h[9 * 64 * 72]; // [k][c][o pad72] bf16 hi
__device__ __nv_bfloat16 g_Wt9l[9 * 64 * 72]; // bf16 lo
__device__ __nv_bfloat16 g_zh[157286400u];    // [n][slot=12800][k=192] bf16 hi
__device__ __nv_bfloat16 g_zl[157286400u];    // bf16 lo
__device__ float g_y[52428800u];              // pre-BN y; later reused for TCN z
__device__ float g_y2[52428800u];             // post BN1+residual+relu
__device__ float g_bnS[64u * 16384u];
__device__ float g_bnQ[64u * 16384u];
__device__ float g_stats[256];                // [off+c]=mean, [off+64+c]=rstd
__device__ float g_meanT[64 * 64 * 25];
__device__ float g_gs[64 * 25];               // 1+sigmoid spatial gate
__device__ float g_meanV[64 * 64 * 512];
__device__ float g_gt[64 * 512];              // 1+sigmoid temporal gate
__device__ float g_gc[64 * 64];               // 1+sigmoid channel gate

// ---------------- mma helpers ----------------
__device__ __forceinline__ unsigned su32(const void* p) {
    return (unsigned)__cvta_generic_to_shared(p);
}
__device__ __forceinline__ void ldsm4(unsigned addr, unsigned* r) {
    asm volatile("ldmatrix.sync.aligned.m8n8.x4.shared.b16 {%0,%1,%2,%3}, [%4];"
                 : "=r"(r[0]), "=r"(r[1]), "=r"(r[2]), "=r"(r[3]) : "r"(addr));
}
__device__ __forceinline__ void ldsm4t(unsigned addr, unsigned* r) {
    asm volatile("ldmatrix.sync.aligned.m8n8.x4.trans.shared.b16 {%0,%1,%2,%3}, [%4];"
                 : "=r"(r[0]), "=r"(r[1]), "=r"(r[2]), "=r"(r[3]) : "r"(addr));
}
__device__ __forceinline__ void mma16816(float* d, const unsigned* a, const unsigned* b) {
    asm volatile("mma.sync.aligned.m16n8k16.row.col.f32.bf16.bf16.f32 "
                 "{%0,%1,%2,%3}, {%4,%5,%6,%7}, {%8,%9}, {%0,%1,%2,%3};"
                 : "+f"(d[0]), "+f"(d[1]), "+f"(d[2]), "+f"(d[3])
                 : "r"(a[0]), "r"(a[1]), "r"(a[2]), "r"(a[3]), "r"(b[0]), "r"(b[1]));
}
// pack two floats into bf16x2 hi-plane and lo-plane words
__device__ __forceinline__ void split2(float a, float b, unsigned& uh, unsigned& ul) {
    __nv_bfloat16 ha = __float2bfloat16(a), hb = __float2bfloat16(b);
    __nv_bfloat16 la = __float2bfloat16(a - __bfloat162float(ha));
    __nv_bfloat16 lb = __float2bfloat16(b - __bfloat162float(hb));
    uh = ((unsigned)__bfloat16_as_ushort(hb) << 16) | __bfloat16_as_ushort(ha);
    ul = ((unsigned)__bfloat16_as_ushort(lb) << 16) | __bfloat16_as_ushort(la);
}

// ---------------- fused fa/fb projection (MMA) + Gram partials + weight prep ----------------
// grid (64 n, 8 seg); 256 thr. Blocks with n==0 also transpose/split Wd + tcn weights
// (consumers k_gcn2/k_tcn launch strictly later).
#define FAB_SMEM 106880
__global__ void __launch_bounds__(256) k_fabgram(
    const float* __restrict__ x, const float* __restrict__ Wa, const float* __restrict__ ba,
    const float* __restrict__ Wb, const float* __restrict__ bb,
    const float* __restrict__ Wd, const float* __restrict__ tw)
{
    extern __shared__ char fraw[];
    __nv_bfloat16* Xh = (__nv_bfloat16*)fraw;            // [64 c][128 col]; Xl +8192 el
    __nv_bfloat16* Wh = (__nv_bfloat16*)(fraw + 32768);  // [96 row][64 c]; Wl +6144 el
    float* fs   = (float*)(fraw + 57344);                // [6][64 kl][32 v]
    float* bias = (float*)(fraw + 106496);               // [96]
    int n = blockIdx.x, seg = blockIdx.y, tid = threadIdx.x;
    int tseg0 = seg * 64;
    int wid = tid >> 5, lane = tid & 31;

    // ---- weight prep (merged from k_prep), n==0 blocks only ----
    if (n == 0) {
        int base = seg * 256 + tid;
        for (int i = base; i < 192 * 72; i += 2048) {
            int k = i / 72, o = i % 72;
            float w = 0.f;
            if (o < 64) { int s = k >> 6, c = k & 63; w = Wd[s * 4096 + o * 64 + c]; }
            __nv_bfloat16 h = __float2bfloat16(w);
            g_Wd2h[i] = h;
            g_Wd2l[i] = __float2bfloat16(w - __bfloat162float(h));
        }
        for (int i = base; i < 9 * 64 * 72; i += 2048) {
            int k = i / 4608, r = i % 4608, c = r / 72, o = r % 72;
            float w = (o < 64) ? tw[o * 576 + c * 9 + k] : 0.f;
            __nv_bfloat16 h = __float2bfloat16(w);
            g_Wt9h[i] = h;
            g_Wt9l[i] = __float2bfloat16(w - __bfloat162float(h));
        }
    }

    // stage W split + bias
    for (int idx = tid; idx < 96 * 64; idx += 256) {
        int sr = idx >> 6, c = idx & 63;
        int s = sr >> 5, r = sr & 31;
        float w = (r < 16) ? Wa[s * 1024 + r * 64 + c] : Wb[s * 1024 + (r - 16) * 64 + c];
        __nv_bfloat16 h = __float2bfloat16(w);
        Wh[idx] = h;
        Wh[6144 + idx] = __float2bfloat16(w - __bfloat162float(h));
    }
    if (tid < 96) {
        int s = tid >> 5, r = tid & 31;
        bias[tid] = (r < 16) ? ba[s * 16 + r] : bb[s * 16 + (r - 16)];
    }

    int gv = tid >> 3, gw4 = (tid & 7) * 4;
    float gacc[3][4];
#pragma unroll
    for (int s = 0; s < 3; s++)
#pragma unroll
        for (int q = 0; q < 4; q++) gacc[s][q] = 0.f;

    int arow = lane & 15, acol8 = (lane >> 4) << 3;
    unsigned baseX = su32(Xh), baseW = su32(Wh);

    for (int sub = 0; sub < 16; sub++) {
        int t0 = tseg0 + sub * 4;
        __syncthreads();   // prev gram done before X overwrite (also covers W staging on sub 0)
        for (int idx = tid; idx < 8192; idx += 256) {
            int c = idx >> 7, r = idx & 127, t = r >> 5, v = r & 31;
            float val = (v < 25) ? x[(((size_t)n * 64 + c) * 512 + t0 + t) * 25 + v] : 0.f;
            __nv_bfloat16 h = __float2bfloat16(val);
            Xh[idx] = h;
            Xh[8192 + idx] = __float2bfloat16(val - __bfloat162float(h));
        }
        __syncthreads();
        // proj: warp owns col-group ng=wid; B fragments loaded once, reused over 6 (s,m) tiles
        {
            int ng = wid;
            unsigned bh[4][4], bl[4][4];
#pragma unroll
            for (int ks = 0; ks < 4; ks++) {
                unsigned ba_ = baseX + (unsigned)(((ks * 16 + arow) * 128 + ng * 16 + acol8) * 2);
                ldsm4t(ba_, bh[ks]);
                ldsm4t(ba_ + 16384u, bl[ks]);
            }
#pragma unroll
            for (int sm = 0; sm < 6; sm++) {
                int s = sm >> 1, m = sm & 1;
                float acc[8];
#pragma unroll
                for (int q = 0; q < 8; q++) acc[q] = 0.f;
#pragma unroll
                for (int ks = 0; ks < 4; ks++) {
                    unsigned ah[4], al[4];
                    unsigned aa = baseW + (unsigned)(((s * 32 + m * 16 + arow) * 64 + ks * 16 + acol8) * 2);
                    ldsm4(aa, ah);
                    ldsm4(aa + 12288u, al);
                    mma16816(&acc[0], ah, &bh[ks][0]);
                    mma16816(&acc[0], ah, &bl[ks][0]);
                    mma16816(&acc[0], al, &bh[ks][0]);
                    mma16816(&acc[4], ah, &bh[ks][2]);
                    mma16816(&acc[4], ah, &bl[ks][2]);
                    mma16816(&acc[4], al, &bh[ks][2]);
                }
                int r0 = lane >> 2;
                float b0 = bias[s * 32 + m * 16 + r0];
                float b8 = bias[s * 32 + m * 16 + r0 + 8];
                float* fsb = &fs[(s * 2 + m) * 2048];
#pragma unroll
                for (int h = 0; h < 2; h++) {
                    int col = ng * 16 + h * 8 + ((lane & 3) << 1);
                    int t = col >> 5, v = col & 31;
                    float* fp = &fsb[(t * 16 + r0) * 32];
                    fp[v] = acc[h * 4 + 0] + b0;
                    fp[v + 1] = acc[h * 4 + 1] + b0;
                    float* fp8 = &fsb[(t * 16 + r0 + 8) * 32];
                    fp8[v] = acc[h * 4 + 2] + b8;
                    fp8[v + 1] = acc[h * 4 + 3] + b8;
                }
            }
        }
        __syncthreads();
        // gram accumulate over 64 kl rows (scalar)
#pragma unroll
        for (int s = 0; s < 3; s++) {
            const float* fap = &fs[(s * 2 + 0) * 2048];
            const float* fbp = &fs[(s * 2 + 1) * 2048];
            for (int kk = 0; kk < 64; kk++) {
                float fav = fap[kk * 32 + gv];
                float4 f4 = *(const float4*)&fbp[kk * 32 + gw4];
                gacc[s][0] += fav * f4.x; gacc[s][1] += fav * f4.y;
                gacc[s][2] += fav * f4.z; gacc[s][3] += fav * f4.w;
            }
        }
    }
#pragma unroll
    for (int s = 0; s < 3; s++) {
        float* p = &g_Apart[((size_t)((n * 3 + s) * 8 + seg)) * 1024 + gv * 32 + gw4];
        p[0] = gacc[s][0]; p[1] = gacc[s][1]; p[2] = gacc[s][2]; p[3] = gacc[s][3];
    }
}

__global__ void k_gram2(const float* __restrict__ PA, const float* __restrict__ alpha) {
    int ns = blockIdx.x; int s = ns % 3;
    float al = alpha[0];
    for (int p = threadIdx.x; p < 625; p += 256) {
        int v = p / 25, w = p % 25;
        float sum = 0;
        for (int seg = 0; seg < 8; seg++)
            sum += g_Apart[((size_t)ns * 8 + seg) * 1024 + v * 32 + w];
        float A1 = tanhf(sum * (1.0f / 8192.0f));
        g_Aeff[ns * 625 + p] = PA[s * 625 + p] + al * A1;
    }
}

// ---------------- GCN stage1 (scalar): z[slot][k] = x·Ae, bf16 split to gmem ----------------
#define GCN1_SMEM 62800
__global__ void __launch_bounds__(256, 3) k_gcn1(const float* __restrict__ x) {
    extern __shared__ char s1raw[];
    float* xT = (float*)s1raw;                       // [tv=200][68c] 54400B
    float* ae = (float*)(s1raw + 54400);             // [3][25][28]   8400B
    int tcb = blockIdx.x, n = blockIdx.y;
    int t0 = tcb * 8, tid = threadIdx.x;

    for (int idx = tid; idx < 12800; idx += 256) {
        int c = idx / 200, tv = idx % 200;
        xT[tv * 68 + c] = x[(((size_t)n * 64 + c) * 512 + t0 + tv / 25) * 25 + tv % 25];
    }
    for (int idx = tid; idx < 2100; idx += 256) {
        int s = idx / 700, r = idx % 700, v = r / 28, w = r % 28;
        ae[idx] = (w < 25) ? g_Aeff[(size_t)(n * 3 + s) * 625 + v * 25 + w] : 0.f;
    }
    __syncthreads();

    int co = (tid & 7) * 8, w = tid >> 3;   // w 0..31, active if <25
    unsigned* zh32 = (unsigned*)g_zh;
    unsigned* zl32 = (unsigned*)g_zl;

    if (w < 25) {
        for (int t = 0; t < 8; t++) {
            float acc[3][8];
#pragma unroll
            for (int s = 0; s < 3; s++)
#pragma unroll
                for (int i = 0; i < 8; i++) acc[s][i] = 0.f;
            for (int v = 0; v < 25; v++) {
                float4 X0 = *(const float4*)&xT[(t * 25 + v) * 68 + co];
                float4 X1 = *(const float4*)&xT[(t * 25 + v) * 68 + co + 4];
#pragma unroll
                for (int s = 0; s < 3; s++) {
                    float e = ae[s * 700 + v * 28 + w];
                    acc[s][0] += X0.x * e; acc[s][1] += X0.y * e;
                    acc[s][2] += X0.z * e; acc[s][3] += X0.w * e;
                    acc[s][4] += X1.x * e; acc[s][5] += X1.y * e;
                    acc[s][6] += X1.z * e; acc[s][7] += X1.w * e;
                }
            }
            size_t slotw = ((size_t)n * 12800 + (size_t)(t0 + t) * 25 + w) * 96;
#pragma unroll
            for (int s = 0; s < 3; s++) {
                unsigned uh0, ul0, uh1, ul1, uh2, ul2, uh3, ul3;
                split2(acc[s][0], acc[s][1], uh0, ul0);
                split2(acc[s][2], acc[s][3], uh1, ul1);
                split2(acc[s][4], acc[s][5], uh2, ul2);
                split2(acc[s][6], acc[s][7], uh3, ul3);
                size_t woff = slotw + s * 32 + (co >> 1);
                *(uint4*)&zh32[woff] = make_uint4(uh0, uh1, uh2, uh3);
                *(uint4*)&zl32[woff] = make_uint4(ul0, ul1, ul2, ul3);
            }
        }
    }
}

// ---------------- GCN stage2: 64-slot chunks, 2 CTAs/SM, zout overlays A ----------------
// grid (200 slot-chunks of 64, 64 n), 512 thr. 16 MMA tiles = 1/warp, K=192.
#define GCN2_SMEM 106496
__global__ void __launch_bounds__(512, 2) k_gcn2() {
    extern __shared__ char s2raw[];
    __nv_bfloat16* Azh = (__nv_bfloat16*)s2raw;              // [64][200] hi; lo +25600B
    float* zout = (float*)s2raw;                              // overlay post-MMA: [64 o][72]
    int blk = blockIdx.x, n = blockIdx.y;
    int slot0 = blk * 64, tid = threadIdx.x;
    int wid = tid >> 5, lane = tid & 31;

    // stage A (z tile) hi/lo
    {
        unsigned* dh = (unsigned*)s2raw;
        unsigned* dl = (unsigned*)(s2raw + 25600);
        const unsigned* shp = (const unsigned*)g_zh;
        const unsigned* slp = (const unsigned*)g_zl;
        for (int idx = tid; idx < 6144; idx += 512) {
            int row = idx / 96, kp = idx % 96;
            size_t src = ((size_t)n * 12800 + slot0 + row) * 96 + kp;
            dh[row * 100 + kp] = shp[src];
            dl[row * 100 + kp] = slp[src];
        }
    }
    // stage W hi/lo
    {
        unsigned* dh = (unsigned*)(s2raw + 51200);
        unsigned* dl = (unsigned*)(s2raw + 78848);
        const unsigned* shp = (const unsigned*)g_Wd2h;
        const unsigned* slp = (const unsigned*)g_Wd2l;
        for (int idx = tid; idx < 6912; idx += 512) { dh[idx] = shp[idx]; dl[idx] = slp[idx]; }
    }
    __syncthreads();

    int ng = wid & 3, m = wid >> 2;   // 1 tile per warp: m-slot-tile x o-group
    float acc[8];
#pragma unroll
    for (int i = 0; i < 8; i++) acc[i] = 0.f;

    unsigned baseA = su32(Azh), baseW = su32(s2raw + 51200);
    int arow = lane & 15, acol8 = (lane >> 4) << 3;
#pragma unroll
    for (int ks = 0; ks < 12; ks++) {
        int k0 = ks * 16;
        unsigned bh[4], bl[4], ah[4], al[4];
        unsigned baddr = baseW + (unsigned)(((k0 + arow) * 72 + ng * 16 + acol8) * 2);
        ldsm4t(baddr, bh);
        ldsm4t(baddr + 27648u, bl);
        unsigned aaddr = baseA + (unsigned)(((m * 16 + arow) * 200 + k0 + acol8) * 2);
        ldsm4(aaddr, ah);
        ldsm4(aaddr + 25600u, al);
        mma16816(&acc[0], ah, &bh[0]);
        mma16816(&acc[0], ah, &bl[0]);
        mma16816(&acc[0], al, &bh[0]);
        mma16816(&acc[4], ah, &bh[2]);
        mma16816(&acc[4], ah, &bl[2]);
        mma16816(&acc[4], al, &bh[2]);
    }
    __syncthreads();   // all MMA reads of A done; overlay zout onto A region
    {
        int r0 = m * 16 + (lane >> 2);
#pragma unroll
        for (int h = 0; h < 2; h++) {
            int o0 = ng * 16 + h * 8 + ((lane & 3) << 1);
            zout[o0 * 72 + r0] = acc[h * 4 + 0];
            zout[(o0 + 1) * 72 + r0] = acc[h * 4 + 1];
            zout[o0 * 72 + r0 + 8] = acc[h * 4 + 2];
            zout[(o0 + 1) * 72 + r0 + 8] = acc[h * 4 + 3];
        }
    }
    __syncthreads();
    // coalesced global store
    for (int idx = tid; idx < 4096; idx += 512) {
        int o = idx >> 6, sl = idx & 63;
        g_y[(size_t)(n * 64 + o) * 12800 + slot0 + sl] = zout[o * 72 + sl];
    }
    // BN1 partials (red region after zout: zout 64*72*4=18432B)
    float* red = (float*)(s2raw + 20480);
    {
        int o = tid >> 3, sub = tid & 7;
        float a = 0, b = 0;
        for (int sl = sub; sl < 64; sl += 8) {
            float v = zout[o * 72 + sl];
            a += v; b += v * v;
        }
        red[tid] = a; red[512 + tid] = b;
    }
    __syncthreads();
    if (tid < 64) {
        float a = 0, b = 0;
        for (int p = 0; p < 8; p++) { a += red[tid * 8 + p]; b += red[512 + tid * 8 + p]; }
        g_bnS[(size_t)tid * 16384 + n * 200 + blk] = a;
        g_bnQ[(size_t)tid * 16384 + n * 200 + blk] = b;
    }
}

__global__ void k_bnfin(int cnt, int off) {
    __shared__ float s1[256], s2[256];
    int c = blockIdx.x, tid = threadIdx.x;
    float a = 0, b = 0;
    for (int i = tid; i < cnt; i += 256) {
        a += g_bnS[(size_t)c * 16384 + i];
        b += g_bnQ[(size_t)c * 16384 + i];
    }
    s1[tid] = a; s2[tid] = b; __syncthreads();
    for (int st = 128; st > 0; st >>= 1) {
        if (tid < st) { s1[tid] += s1[tid + st]; s2[tid] += s2[tid + st]; }
        __syncthreads();
    }
    if (tid == 0) {
        float m = s1[0] / 819200.0f;
        float v = s2[0] / 819200.0f - m * m;
        g_stats[off + c] = m;
        g_stats[off + 64 + c] = rsqrtf(v + 1e-5f);
    }
}

// BN1 apply + residual + relu -> g_y2, fused T-mean partials -> g_meanT
__global__ void __launch_bounds__(256) k_bnapply_mt(
    const float* __restrict__ gm, const float* __restrict__ bt, const float* __restrict__ x)
{
    __shared__ float red[8 * 33];
    int nc = blockIdx.x, tid = threadIdx.x, lane = tid & 31, tg = tid >> 5;
    int c = nc & 63;
    float m = g_stats[c], r = g_stats[64 + c];
    float sc = r * gm[c], sb = bt[c] - m * sc;
    float a = 0;
    if (lane < 25) {
        size_t base = (size_t)nc * 12800 + lane;
        for (int t = tg; t < 512; t += 8) {
            float y = g_y[base + t * 25];
            float o = fmaxf(y * sc + sb + x[base + t * 25], 0.f);
            g_y2[base + t * 25] = o;
            a += o;
        }
        red[tg * 33 + lane] = a;
    }
    __syncthreads();
    if (tid < 25) {
        float s = 0;
        for (int g = 0; g < 8; g++) s += red[g * 33 + tid];
        g_meanT[nc * 25 + tid] = s * (1.f / 512.f);
    }
}

// ---------------- attention chain ----------------
__global__ void k_sattn(const float* __restrict__ saw, const float* __restrict__ sab) {
    int n = blockIdx.x, v = threadIdx.x;
    if (v < 25) {
        float acc = sab[0];
        for (int c = 0; c < 64; c++) {
            const float* m = &g_meanT[(n * 64 + c) * 25];
            const float* w = &saw[c * 25];
#pragma unroll
            for (int j = 0; j < 25; j++) {
                int vv = v + j - 12;
                if (vv >= 0 && vv < 25) acc += w[j] * m[vv];
            }
        }
        g_gs[n * 25 + v] = 1.f + 1.f / (1.f + expf(-acc));
    }
}

__global__ void __launch_bounds__(256) k_meanV() {
    __shared__ float sgs[25];
    int nc = blockIdx.x, tid = threadIdx.x;
    int n = nc >> 6;
    if (tid < 25) sgs[tid] = g_gs[n * 25 + tid];
    __syncthreads();
    for (int t = tid; t < 512; t += 256) {
        const float* row = &g_y2[(size_t)nc * 12800 + t * 25];
        float a = 0;
#pragma unroll
        for (int v = 0; v < 25; v++) a += row[v] * sgs[v];
        g_meanV[nc * 512 + t] = a * (1.f / 25.f);
    }
}

__global__ void k_tattn(const float* __restrict__ taw, const float* __restrict__ tab) {
    int n = blockIdx.x, tid = threadIdx.x;
    for (int t = tid; t < 512; t += 256) {
        float acc = tab[0];
        for (int c = 0; c < 64; c++) {
            const float* m = &g_meanV[(n * 64 + c) * 512];
            const float* w = &taw[c * 9];
#pragma unroll
            for (int j = 0; j < 9; j++) {
                int tt = t + j - 4;
                if (tt >= 0 && tt < 512) acc += w[j] * m[tt];
            }
        }
        g_gt[n * 512 + t] = 1.f + 1.f / (1.f + expf(-acc));
    }
}

__global__ void k_cse(const float* __restrict__ f1w, const float* __restrict__ f1b,
                      const float* __restrict__ f2w, const float* __restrict__ f2b) {
    __shared__ float sm3[64], sh[32];
    int n = blockIdx.x, c = threadIdx.x;
    const float* m = &g_meanV[(n * 64 + c) * 512];
    const float* gt = &g_gt[n * 512];
    float a = 0;
    for (int t = 0; t < 512; t++) a += m[t] * gt[t];
    sm3[c] = a * (1.f / 512.f);
    __syncthreads();
    if (c < 32) {
        float h = f1b[c];
        for (int k = 0; k < 64; k++) h += f1w[c * 64 + k] * sm3[k];
        sh[c] = fmaxf(h, 0.f);
    }
    __syncthreads();
    float o = f2b[c];
    for (int j = 0; j < 32; j++) o += f2w[c * 32 + j] * sh[j];
    g_gc[n * 64 + c] = 1.f + 1.f / (1.f + expf(-o));
}

// ---------------- TCN via mma.sync bf16-split + BN2 partial epilogue ----------------
#define TCN_SMEM 189440
__global__ void __launch_bounds__(512) k_tcn() {
    extern __shared__ char smemraw[];
    __nv_bfloat16* Ah = (__nv_bfloat16*)smemraw;                 // [408][72]
    __nv_bfloat16* Wh = (__nv_bfloat16*)(smemraw + 117504);      // [64][72]
    __nv_bfloat16* Wl = (__nv_bfloat16*)(smemraw + 126720);
    float* zout = (float*)(smemraw + 135936);                    // [64][209]
    __shared__ float gsg[25], gtg[17], gcg[64];
    int tcb = blockIdx.x, n = blockIdx.y;
    int t0 = tcb * 8, tid = threadIdx.x;
    int wid = tid >> 5, lane = tid & 31;

    if (tid < 25) gsg[tid] = g_gs[n * 25 + tid];
    if (tid >= 32 && tid < 49) {
        int tin = t0 - 4 + (tid - 32);
        gtg[tid - 32] = (tin >= 0 && tin < 512) ? g_gt[n * 512 + tin] : 0.f;
    }
    if (tid >= 64 && tid < 128) gcg[tid - 64] = g_gc[n * 64 + (tid - 64)];
    __syncthreads();

    for (int idx = tid; idx < 408 * 32; idx += 512) {
        int cp = idx / 408, s = idx - cp * 408;
        int tvg = (t0 - 4) * 25 + s;
        float v0 = 0.f, v1 = 0.f;
        if (tvg >= 0 && tvg < 12800) {
            float g = gsg[s % 25] * gtg[s / 25];
            v0 = g_y2[(size_t)(n * 64 + 2 * cp) * 12800 + tvg] * g * gcg[2 * cp];
            v1 = g_y2[(size_t)(n * 64 + 2 * cp + 1) * 12800 + tvg] * g * gcg[2 * cp + 1];
        }
        unsigned uh, ul;
        split2(v0, v1, uh, ul);
        *(unsigned*)&Ah[s * 72 + 2 * cp] = uh;
        *(unsigned*)&Ah[29376 + s * 72 + 2 * cp] = ul;
    }

    int ng = wid & 3, w4 = wid >> 2;
    int nbase = ng * 16;
    int mt[4], cnt = 0;
    for (int m = w4; m < 13; m += 4) mt[cnt++] = m;
    float acc[4][8];
#pragma unroll
    for (int q = 0; q < 4; q++)
#pragma unroll
        for (int i = 0; i < 8; i++) acc[q][i] = 0.f;

    unsigned baseA = su32(Ah), baseW = su32(Wh);
    int arow = lane & 15, acol8 = (lane >> 4) << 3;

    for (int tap = 0; tap < 9; tap++) {
        __syncthreads();
        for (int idx = tid; idx < 4608; idx += 512) {
            Wh[idx] = g_Wt9h[tap * 4608 + idx];
            Wl[idx] = g_Wt9l[tap * 4608 + idx];
        }
        __syncthreads();
#pragma unroll
        for (int ks = 0; ks < 4; ks++) {
            int c0 = ks * 16;
            unsigned bh[4], bl[4];
            unsigned baddr = baseW + (unsigned)(((c0 + arow) * 72 + nbase + acol8) * 2);
            ldsm4t(baddr, bh);
            ldsm4t(baddr + 9216u, bl);
#pragma unroll
            for (int q = 0; q < 4; q++) {
                if (q >= cnt) break;
                int rb = mt[q] * 16 + 25 * tap;
                unsigned aaddr = baseA + (unsigned)(((rb + arow) * 72 + c0 + acol8) * 2);
                unsigned ah[4], al[4];
                ldsm4(aaddr, ah);
                ldsm4(aaddr + 58752u, al);
                mma16816(&acc[q][0], ah, &bh[0]);
                mma16816(&acc[q][0], ah, &bl[0]);
                mma16816(&acc[q][0], al, &bh[0]);
                mma16816(&acc[q][4], ah, &bh[2]);
                mma16816(&acc[q][4], ah, &bl[2]);
                mma16816(&acc[q][4], al, &bh[2]);
            }
        }
    }
    __syncthreads();
#pragma unroll
    for (int q = 0; q < 4; q++) {
        if (q >= cnt) break;
#pragma unroll
        for (int h = 0; h < 2; h++) {
            int o0 = nbase + h * 8 + ((lane & 3) << 1);
            int r0 = mt[q] * 16 + (lane >> 2);
            zout[o0 * 209 + r0] = acc[q][h * 4 + 0];
            zout[(o0 + 1) * 209 + r0] = acc[q][h * 4 + 1];
            zout[o0 * 209 + r0 + 8] = acc[q][h * 4 + 2];
            zout[(o0 + 1) * 209 + r0 + 8] = acc[q][h * 4 + 3];
        }
    }
    __syncthreads();
    for (int idx = tid; idx < 64 * 200; idx += 512) {
        int o = idx / 200, sl = idx - o * 200;
        g_y[((size_t)(n * 64 + o) * 512 + t0) * 25 + sl] = zout[o * 209 + sl];
    }
    float* red = (float*)Wh;
    {
        int o = tid >> 3, sub = tid & 7;
        float a = 0, b = 0;
        for (int sl = sub; sl < 200; sl += 8) {
            float v = zout[o * 209 + sl];
            a += v; b += v * v;
        }
        red[tid] = a; red[512 + tid] = b;
    }
    __syncthreads();
    if (tid < 64) {
        float a = 0, b = 0;
        for (int p = 0; p < 8; p++) { a += red[tid * 8 + p]; b += red[512 + tid * 8 + p]; }
        g_bnS[(size_t)tid * 16384 + n * 64 + tcb] = a;
        g_bnQ[(size_t)tid * 16384 + n * 64 + tcb] = b;
    }
}

// final: out = relu(bn2(g_y) + x), vectorized
__global__ void __launch_bounds__(256) k_bnapply2(
    const float* __restrict__ gm, const float* __restrict__ bt,
    const float* __restrict__ x, float* __restrict__ out)
{
    size_t i4 = (size_t)blockIdx.x * 256 + threadIdx.x;
    size_t flat = i4 * 4;
    int c = (int)((flat / 12800) % 64);
    float m = g_stats[128 + c], r = g_stats[192 + c];
    float sc = r * gm[c];
    float sb = bt[c] - m * sc;
    float4 Y = *(const float4*)&g_y[flat];
    float4 X = *(const float4*)&x[flat];
    float4 O;
    O.x = fmaxf(Y.x * sc + sb + X.x, 0.f);
    O.y = fmaxf(Y.y * sc + sb + X.y, 0.f);
    O.z = fmaxf(Y.z * sc + sb + X.z, 0.f);
    O.w = fmaxf(Y.w * sc + sb + X.w, 0.f);
    *(float4*)&out[flat] = O;
}

// ---------------- launcher ----------------
extern "C" void kernel_launch(void* const* d_in, const int* in_sizes, int n_in,
                              void* d_out, int out_size) {
    const float* x   = (const float*)d_in[0];
    const float* PA  = (const float*)d_in[1];
    const float* alp = (const float*)d_in[2];
    const float* Wa  = (const float*)d_in[3];
    const float* ba  = (const float*)d_in[4];
    const float* Wb  = (const float*)d_in[5];
    const float* bb  = (const float*)d_in[6];
    const float* Wd  = (const float*)d_in[7];
    const float* bng = (const float*)d_in[9];
    const float* bnb = (const float*)d_in[10];
    const float* saw = (const float*)d_in[11];
    const float* sab = (const float*)d_in[12];
    const float* taw = (const float*)d_in[13];
    const float* tab = (const float*)d_in[14];
    const float* f1w = (const float*)d_in[15];
    const float* f1b = (const float*)d_in[16];
    const float* f2w = (const float*)d_in[17];
    const float* f2b = (const float*)d_in[18];
    const float* tw  = (const float*)d_in[19];
    const float* tbg = (const float*)d_in[21];
    const float* tbb = (const float*)d_in[22];
    float* out = (float*)d_out;

    cudaFuncSetAttribute(k_fabgram, cudaFuncAttributeMaxDynamicSharedMemorySize, FAB_SMEM);
    cudaFuncSetAttribute(k_gcn1, cudaFuncAttributeMaxDynamicSharedMemorySize, GCN1_SMEM);
    cudaFuncSetAttribute(k_gcn2, cudaFuncAttributeMaxDynamicSharedMemorySize, GCN2_SMEM);
    cudaFuncSetAttribute(k_tcn, cudaFuncAttributeMaxDynamicSharedMemorySize, TCN_SMEM);

    k_fabgram<<<dim3(64, 8), 256, FAB_SMEM>>>(x, Wa, ba, Wb, bb, Wd, tw);
    k_gram2<<<192, 256>>>(PA, alp);
    k_gcn1<<<dim3(64, 64), 256, GCN1_SMEM>>>(x);
    k_gcn2<<<dim3(200, 64), 512, GCN2_SMEM>>>();
    k_bnfin<<<64, 256>>>(12800, 0);
    k_bnapply_mt<<<4096, 256>>>(bng, bnb, x);
    k_sattn<<<64, 32>>>(saw, sab);
    k_meanV<<<4096, 256>>>();
    k_tattn<<<64, 256>>>(taw, tab);
    k_cse<<<64, 64>>>(f1w, f1b, f2w, f2b);
    k_tcn<<<dim3(64, 64), 512, TCN_SMEM>>>();
    k_bnfin<<<64, 256>>>(4096, 128);
    k_bnapply2<<<51200, 256>>>(tbg, tbb, x, out);
}

// round 17
// speedup vs baseline: 1.0556x; 1.0556x over previous
#include <cuda_runtime.h>
#include <cuda_bf16.h>
#include <cstdint>
#include <math.h>

// dims: N=64, C=64, T=512, V=25, S=3, I=16
// ---------------- device scratch (no cudaMalloc allowed) ----------------
__device__ float g_Apart[1536u * 1024u];      // [(n*3+s)*8+seg][v32*32]
__device__ float g_Aeff[192 * 625];           // [n*3+s][v][w]
__device__ __nv_bfloat16 g_Wd2h[192 * 72];    // [k=s*64+c][o pad72] bf16 hi
__device__ __nv_bfloat16 g_Wd2l[192 * 72];    // bf16 lo
__device__ __nv_bfloat16 g_Wt9h[9 * 64 * 72]; // [k][c][o pad72] bf16 hi
__device__ __nv_bfloat16 g_Wt9l[9 * 64 * 72]; // bf16 lo
__device__ __nv_bfloat16 g_zh[157286400u];    // [n][slot=12800][k=192] bf16 hi
__device__ __nv_bfloat16 g_zl[157286400u];    // bf16 lo
__device__ float g_y[52428800u];              // pre-BN y; later reused for TCN z
__device__ float g_y2[52428800u];             // post BN1+residual+relu
__device__ float g_bnS[64u * 16384u];
__device__ float g_bnQ[64u * 16384u];
__device__ float g_stats[256];                // [off+c]=mean, [off+64+c]=rstd
__device__ float g_meanT[64 * 64 * 25];
__device__ float g_gs[64 * 25];               // 1+sigmoid spatial gate
__device__ float g_meanV[64 * 64 * 512];
__device__ float g_gt[64 * 512];              // 1+sigmoid temporal gate
__device__ float g_gc[64 * 64];               // 1+sigmoid channel gate

// ---------------- mma helpers ----------------
__device__ __forceinline__ unsigned su32(const void* p) {
    return (unsigned)__cvta_generic_to_shared(p);
}
__device__ __forceinline__ void ldsm4(unsigned addr, unsigned* r) {
    asm volatile("ldmatrix.sync.aligned.m8n8.x4.shared.b16 {%0,%1,%2,%3}, [%4];"
                 : "=r"(r[0]), "=r"(r[1]), "=r"(r[2]), "=r"(r[3]) : "r"(addr));
}
__device__ __forceinline__ void ldsm4t(unsigned addr, unsigned* r) {
    asm volatile("ldmatrix.sync.aligned.m8n8.x4.trans.shared.b16 {%0,%1,%2,%3}, [%4];"
                 : "=r"(r[0]), "=r"(r[1]), "=r"(r[2]), "=r"(r[3]) : "r"(addr));
}
__device__ __forceinline__ void mma16816(float* d, const unsigned* a, const unsigned* b) {
    asm volatile("mma.sync.aligned.m16n8k16.row.col.f32.bf16.bf16.f32 "
                 "{%0,%1,%2,%3}, {%4,%5,%6,%7}, {%8,%9}, {%0,%1,%2,%3};"
                 : "+f"(d[0]), "+f"(d[1]), "+f"(d[2]), "+f"(d[3])
                 : "r"(a[0]), "r"(a[1]), "r"(a[2]), "r"(a[3]), "r"(b[0]), "r"(b[1]));
}
// pack two floats into bf16x2 hi-plane and lo-plane words
__device__ __forceinline__ void split2(float a, float b, unsigned& uh, unsigned& ul) {
    __nv_bfloat16 ha = __float2bfloat16(a), hb = __float2bfloat16(b);
    __nv_bfloat16 la = __float2bfloat16(a - __bfloat162float(ha));
    __nv_bfloat16 lb = __float2bfloat16(b - __bfloat162float(hb));
    uh = ((unsigned)__bfloat16_as_ushort(hb) << 16) | __bfloat16_as_ushort(ha);
    ul = ((unsigned)__bfloat16_as_ushort(lb) << 16) | __bfloat16_as_ushort(la);
}

// ---------------- fused fa/fb projection (MMA) + Gram (MMA) + weight prep ----------------
// grid (64 n, 8 seg); 256 thr. n==0 blocks also transpose/split Wd + tcn weights.
// fs stored as bf16 hi/lo [6][64 kl][32 v]; Gram per sub: 12 m16n16 tiles on warps 0..5,
// accumulators persistent across 16 subs.
#define FAB_SMEM 106880
__global__ void __launch_bounds__(256) k_fabgram(
    const float* __restrict__ x, const float* __restrict__ Wa, const float* __restrict__ ba,
    const float* __restrict__ Wb, const float* __restrict__ bb,
    const float* __restrict__ Wd, const float* __restrict__ tw)
{
    extern __shared__ char fraw[];
    __nv_bfloat16* Xh  = (__nv_bfloat16*)fraw;            // [64 c][128 col]; Xl +8192 el
    __nv_bfloat16* Wh  = (__nv_bfloat16*)(fraw + 32768);  // [96 row][64 c]; Wl +6144 el
    __nv_bfloat16* fsh = (__nv_bfloat16*)(fraw + 57344);  // [6][64 kl][32 v]; fsl +12288 el
    __nv_bfloat16* fsl = fsh + 12288;
    float* bias = (float*)(fraw + 106496);                // [96]
    int n = blockIdx.x, seg = blockIdx.y, tid = threadIdx.x;
    int tseg0 = seg * 64;
    int wid = tid >> 5, lane = tid & 31;

    // weight prep (merged), n==0 blocks only
    if (n == 0) {
        int base = seg * 256 + tid;
        for (int i = base; i < 192 * 72; i += 2048) {
            int k = i / 72, o = i % 72;
            float w = 0.f;
            if (o < 64) { int s = k >> 6, c = k & 63; w = Wd[s * 4096 + o * 64 + c]; }
            __nv_bfloat16 h = __float2bfloat16(w);
            g_Wd2h[i] = h;
            g_Wd2l[i] = __float2bfloat16(w - __bfloat162float(h));
        }
        for (int i = base; i < 9 * 64 * 72; i += 2048) {
            int k = i / 4608, r = i % 4608, c = r / 72, o = r % 72;
            float w = (o < 64) ? tw[o * 576 + c * 9 + k] : 0.f;
            __nv_bfloat16 h = __float2bfloat16(w);
            g_Wt9h[i] = h;
            g_Wt9l[i] = __float2bfloat16(w - __bfloat162float(h));
        }
    }

    // stage W split + bias
    for (int idx = tid; idx < 96 * 64; idx += 256) {
        int sr = idx >> 6, c = idx & 63;
        int s = sr >> 5, r = sr & 31;
        float w = (r < 16) ? Wa[s * 1024 + r * 64 + c] : Wb[s * 1024 + (r - 16) * 64 + c];
        __nv_bfloat16 h = __float2bfloat16(w);
        Wh[idx] = h;
        Wh[6144 + idx] = __float2bfloat16(w - __bfloat162float(h));
    }
    if (tid < 96) {
        int s = tid >> 5, r = tid & 31;
        bias[tid] = (r < 16) ? ba[s * 16 + r] : bb[s * 16 + (r - 16)];
    }

    int arow = lane & 15, acol8 = (lane >> 4) << 3;
    unsigned baseX = su32(Xh), baseW = su32(Wh), baseF = su32(fsh);

    // gram accumulators: warps 0..5 own (s = wid>>1, mv = wid&1), two mw tiles each
    int gs_ = wid >> 1, gmv = wid & 1;
    float accg[2][8];
#pragma unroll
    for (int q = 0; q < 2; q++)
#pragma unroll
        for (int i = 0; i < 8; i++) accg[q][i] = 0.f;

    for (int sub = 0; sub < 16; sub++) {
        int t0 = tseg0 + sub * 4;
        __syncthreads();   // prev gram reads of fs done before proj writes (below)
        for (int idx = tid; idx < 8192; idx += 256) {
            int c = idx >> 7, r = idx & 127, t = r >> 5, v = r & 31;
            float val = (v < 25) ? x[(((size_t)n * 64 + c) * 512 + t0 + t) * 25 + v] : 0.f;
            __nv_bfloat16 h = __float2bfloat16(val);
            Xh[idx] = h;
            Xh[8192 + idx] = __float2bfloat16(val - __bfloat162float(h));
        }
        __syncthreads();
        // proj: warp owns col-group ng=wid; writes fs as bf16 split (bias added first)
        {
            int ng = wid;
            unsigned bh[4][4], bl[4][4];
#pragma unroll
            for (int ks = 0; ks < 4; ks++) {
                unsigned ba_ = baseX + (unsigned)(((ks * 16 + arow) * 128 + ng * 16 + acol8) * 2);
                ldsm4t(ba_, bh[ks]);
                ldsm4t(ba_ + 16384u, bl[ks]);
            }
#pragma unroll
            for (int sm = 0; sm < 6; sm++) {
                int s = sm >> 1, m = sm & 1;
                float acc[8];
#pragma unroll
                for (int q = 0; q < 8; q++) acc[q] = 0.f;
#pragma unroll
                for (int ks = 0; ks < 4; ks++) {
                    unsigned ah[4], al[4];
                    unsigned aa = baseW + (unsigned)(((s * 32 + m * 16 + arow) * 64 + ks * 16 + acol8) * 2);
                    ldsm4(aa, ah);
                    ldsm4(aa + 12288u, al);
                    mma16816(&acc[0], ah, &bh[ks][0]);
                    mma16816(&acc[0], ah, &bl[ks][0]);
                    mma16816(&acc[0], al, &bh[ks][0]);
                    mma16816(&acc[4], ah, &bh[ks][2]);
                    mma16816(&acc[4], ah, &bl[ks][2]);
                    mma16816(&acc[4], al, &bh[ks][2]);
                }
                int r0 = lane >> 2;
                float b0 = bias[s * 32 + m * 16 + r0];
                float b8 = bias[s * 32 + m * 16 + r0 + 8];
                int rowb = (s * 2 + m) * 64;
#pragma unroll
                for (int h = 0; h < 2; h++) {
                    int col = ng * 16 + h * 8 + ((lane & 3) << 1);
                    int t = col >> 5, v = col & 31;   // v even
                    unsigned uh, ul;
                    split2(acc[h * 4 + 0] + b0, acc[h * 4 + 1] + b0, uh, ul);
                    int off = (rowb + t * 16 + r0) * 32 + v;
                    *(unsigned*)&fsh[off] = uh;
                    *(unsigned*)&fsl[off] = ul;
                    split2(acc[h * 4 + 2] + b8, acc[h * 4 + 3] + b8, uh, ul);
                    off = (rowb + t * 16 + r0 + 8) * 32 + v;
                    *(unsigned*)&fsh[off] = uh;
                    *(unsigned*)&fsl[off] = ul;
                }
            }
        }
        __syncthreads();
        // gram via MMA: warps 0..5; A = fa^T (ldsm trans + reg swap), B = fb (trans)
        if (wid < 6) {
            int fa_b = (gs_ * 2 + 0) * 64, fb_b = (gs_ * 2 + 1) * 64;
#pragma unroll
            for (int ks = 0; ks < 4; ks++) {
                int k0 = ks * 16;
                unsigned ar[4], alr[4];
                unsigned aa = baseF + (unsigned)(((fa_b + k0 + arow) * 32 + gmv * 16 + acol8) * 2);
                ldsm4t(aa, ar);
                ldsm4t(aa + 24576u, alr);
                unsigned ah[4] = {ar[0], ar[2], ar[1], ar[3]};
                unsigned al[4] = {alr[0], alr[2], alr[1], alr[3]};
#pragma unroll
                for (int mw = 0; mw < 2; mw++) {
                    unsigned bh[4], bl[4];
                    unsigned bb_ = baseF + (unsigned)(((fb_b + k0 + arow) * 32 + mw * 16 + acol8) * 2);
                    ldsm4t(bb_, bh);
                    ldsm4t(bb_ + 24576u, bl);
                    mma16816(&accg[mw][0], ah, &bh[0]);
                    mma16816(&accg[mw][0], ah, &bl[0]);
                    mma16816(&accg[mw][0], al, &bh[0]);
                    mma16816(&accg[mw][4], ah, &bh[2]);
                    mma16816(&accg[mw][4], ah, &bl[2]);
                    mma16816(&accg[mw][4], al, &bh[2]);
                }
            }
        }
    }
    // store gram fragments to g_Apart (only v,w<25 consumed downstream)
    if (wid < 6) {
        float* p = &g_Apart[((size_t)((n * 3 + gs_) * 8 + seg)) * 1024];
        int v0 = gmv * 16 + (lane >> 2);
#pragma unroll
        for (int mw = 0; mw < 2; mw++) {
#pragma unroll
            for (int h = 0; h < 2; h++) {
                int w0 = mw * 16 + h * 8 + ((lane & 3) << 1);
                p[v0 * 32 + w0] = accg[mw][h * 4 + 0];
                p[v0 * 32 + w0 + 1] = accg[mw][h * 4 + 1];
                p[(v0 + 8) * 32 + w0] = accg[mw][h * 4 + 2];
                p[(v0 + 8) * 32 + w0 + 1] = accg[mw][h * 4 + 3];
            }
        }
    }
}

__global__ void k_gram2(const float* __restrict__ PA, const float* __restrict__ alpha) {
    int ns = blockIdx.x; int s = ns % 3;
    float al = alpha[0];
    for (int p = threadIdx.x; p < 625; p += 256) {
        int v = p / 25, w = p % 25;
        float sum = 0;
        for (int seg = 0; seg < 8; seg++)
            sum += g_Apart[((size_t)ns * 8 + seg) * 1024 + v * 32 + w];
        float A1 = tanhf(sum * (1.0f / 8192.0f));
        g_Aeff[ns * 625 + p] = PA[s * 625 + p] + al * A1;
    }
}

// ---------------- GCN stage1 (scalar): z[slot][k] = x·Ae, bf16 split to gmem ----------------
#define GCN1_SMEM 62800
__global__ void __launch_bounds__(256, 3) k_gcn1(const float* __restrict__ x) {
    extern __shared__ char s1raw[];
    float* xT = (float*)s1raw;                       // [tv=200][68c] 54400B
    float* ae = (float*)(s1raw + 54400);             // [3][25][28]   8400B
    int tcb = blockIdx.x, n = blockIdx.y;
    int t0 = tcb * 8, tid = threadIdx.x;

    for (int idx = tid; idx < 12800; idx += 256) {
        int c = idx / 200, tv = idx % 200;
        xT[tv * 68 + c] = x[(((size_t)n * 64 + c) * 512 + t0 + tv / 25) * 25 + tv % 25];
    }
    for (int idx = tid; idx < 2100; idx += 256) {
        int s = idx / 700, r = idx % 700, v = r / 28, w = r % 28;
        ae[idx] = (w < 25) ? g_Aeff[(size_t)(n * 3 + s) * 625 + v * 25 + w] : 0.f;
    }
    __syncthreads();

    int co = (tid & 7) * 8, w = tid >> 3;
    unsigned* zh32 = (unsigned*)g_zh;
    unsigned* zl32 = (unsigned*)g_zl;

    if (w < 25) {
        for (int t = 0; t < 8; t++) {
            float acc[3][8];
#pragma unroll
            for (int s = 0; s < 3; s++)
#pragma unroll
                for (int i = 0; i < 8; i++) acc[s][i] = 0.f;
            for (int v = 0; v < 25; v++) {
                float4 X0 = *(const float4*)&xT[(t * 25 + v) * 68 + co];
                float4 X1 = *(const float4*)&xT[(t * 25 + v) * 68 + co + 4];
#pragma unroll
                for (int s = 0; s < 3; s++) {
                    float e = ae[s * 700 + v * 28 + w];
                    acc[s][0] += X0.x * e; acc[s][1] += X0.y * e;
                    acc[s][2] += X0.z * e; acc[s][3] += X0.w * e;
                    acc[s][4] += X1.x * e; acc[s][5] += X1.y * e;
                    acc[s][6] += X1.z * e; acc[s][7] += X1.w * e;
                }
            }
            size_t slotw = ((size_t)n * 12800 + (size_t)(t0 + t) * 25 + w) * 96;
#pragma unroll
            for (int s = 0; s < 3; s++) {
                unsigned uh0, ul0, uh1, ul1, uh2, ul2, uh3, ul3;
                split2(acc[s][0], acc[s][1], uh0, ul0);
                split2(acc[s][2], acc[s][3], uh1, ul1);
                split2(acc[s][4], acc[s][5], uh2, ul2);
                split2(acc[s][6], acc[s][7], uh3, ul3);
                size_t woff = slotw + s * 32 + (co >> 1);
                *(uint4*)&zh32[woff] = make_uint4(uh0, uh1, uh2, uh3);
                *(uint4*)&zl32[woff] = make_uint4(ul0, ul1, ul2, ul3);
            }
        }
    }
}

// ---------------- GCN stage2 (R15): 128-slot chunks, MMA + BN1 ----------------
#define GCN2_SMEM 192512
__global__ void __launch_bounds__(512) k_gcn2() {
    extern __shared__ char s2raw[];
    __nv_bfloat16* Azh = (__nv_bfloat16*)s2raw;              // [128][200] 51200B
    __nv_bfloat16* Wh = (__nv_bfloat16*)(s2raw + 102400);    // [192][72]  27648B
    float* zout = (float*)(s2raw + 157696);                  // [64][136]  34816B
    int blk = blockIdx.x, n = blockIdx.y;
    int slot0 = blk * 128, tid = threadIdx.x;
    int wid = tid >> 5, lane = tid & 31;

    {
        unsigned* dh = (unsigned*)s2raw;
        unsigned* dl = (unsigned*)(s2raw + 51200);
        const unsigned* shp = (const unsigned*)g_zh;
        const unsigned* slp = (const unsigned*)g_zl;
        for (int idx = tid; idx < 12288; idx += 512) {
            int row = idx / 96, kp = idx % 96;
            size_t src = ((size_t)n * 12800 + slot0 + row) * 96 + kp;
            dh[row * 100 + kp] = shp[src];
            dl[row * 100 + kp] = slp[src];
        }
    }
    {
        unsigned* dh = (unsigned*)(s2raw + 102400);
        unsigned* dl = (unsigned*)(s2raw + 130048);
        const unsigned* shp = (const unsigned*)g_Wd2h;
        const unsigned* slp = (const unsigned*)g_Wd2l;
        for (int idx = tid; idx < 6912; idx += 512) { dh[idx] = shp[idx]; dl[idx] = slp[idx]; }
    }
    __syncthreads();

    int ng = wid & 3, m0 = wid >> 2;
    float acc[2][8];
#pragma unroll
    for (int q = 0; q < 2; q++)
#pragma unroll
        for (int i = 0; i < 8; i++) acc[q][i] = 0.f;

    unsigned baseA = su32(Azh), baseW = su32(Wh);
    int arow = lane & 15, acol8 = (lane >> 4) << 3;
#pragma unroll
    for (int ks = 0; ks < 12; ks++) {
        int k0 = ks * 16;
        unsigned bh[4], bl[4];
        unsigned baddr = baseW + (unsigned)(((k0 + arow) * 72 + ng * 16 + acol8) * 2);
        ldsm4t(baddr, bh);
        ldsm4t(baddr + 27648u, bl);
#pragma unroll
        for (int q = 0; q < 2; q++) {
            int mt = m0 + q * 4;
            unsigned aaddr = baseA + (unsigned)(((mt * 16 + arow) * 200 + k0 + acol8) * 2);
            unsigned ah[4], al[4];
            ldsm4(aaddr, ah);
            ldsm4(aaddr + 51200u, al);
            mma16816(&acc[q][0], ah, &bh[0]);
            mma16816(&acc[q][0], ah, &bl[0]);
            mma16816(&acc[q][0], al, &bh[0]);
            mma16816(&acc[q][4], ah, &bh[2]);
            mma16816(&acc[q][4], ah, &bl[2]);
            mma16816(&acc[q][4], al, &bh[2]);
        }
    }
    __syncthreads();
#pragma unroll
    for (int q = 0; q < 2; q++) {
        int r0 = (m0 + q * 4) * 16 + (lane >> 2);
#pragma unroll
        for (int h = 0; h < 2; h++) {
            int o0 = ng * 16 + h * 8 + ((lane & 3) << 1);
            zout[o0 * 136 + r0] = acc[q][h * 4 + 0];
            zout[(o0 + 1) * 136 + r0] = acc[q][h * 4 + 1];
            zout[o0 * 136 + r0 + 8] = acc[q][h * 4 + 2];
            zout[(o0 + 1) * 136 + r0 + 8] = acc[q][h * 4 + 3];
        }
    }
    __syncthreads();
    for (int idx = tid; idx < 8192; idx += 512) {
        int o = idx / 128, sl = idx % 128;
        g_y[(size_t)(n * 64 + o) * 12800 + slot0 + sl] = zout[o * 136 + sl];
    }
    float* red = (float*)s2raw;
    {
        int o = tid >> 3, sub = tid & 7;
        float a = 0, b = 0;
        for (int sl = sub; sl < 128; sl += 8) {
            float v = zout[o * 136 + sl];
            a += v; b += v * v;
        }
        red[tid] = a; red[512 + tid] = b;
    }
    __syncthreads();
    if (tid < 64) {
        float a = 0, b = 0;
        for (int p = 0; p < 8; p++) { a += red[tid * 8 + p]; b += red[512 + tid * 8 + p]; }
        g_bnS[(size_t)tid * 16384 + n * 100 + blk] = a;
        g_bnQ[(size_t)tid * 16384 + n * 100 + blk] = b;
    }
}

__global__ void k_bnfin(int cnt, int off) {
    __shared__ float s1[256], s2[256];
    int c = blockIdx.x, tid = threadIdx.x;
    float a = 0, b = 0;
    for (int i = tid; i < cnt; i += 256) {
        a += g_bnS[(size_t)c * 16384 + i];
        b += g_bnQ[(size_t)c * 16384 + i];
    }
    s1[tid] = a; s2[tid] = b; __syncthreads();
    for (int st = 128; st > 0; st >>= 1) {
        if (tid < st) { s1[tid] += s1[tid + st]; s2[tid] += s2[tid + st]; }
        __syncthreads();
    }
    if (tid == 0) {
        float m = s1[0] / 819200.0f;
        float v = s2[0] / 819200.0f - m * m;
        g_stats[off + c] = m;
        g_stats[off + 64 + c] = rsqrtf(v + 1e-5f);
    }
}

// BN1 apply + residual + relu -> g_y2, fused T-mean partials -> g_meanT
__global__ void __launch_bounds__(256) k_bnapply_mt(
    const float* __restrict__ gm, const float* __restrict__ bt, const float* __restrict__ x)
{
    __shared__ float red[8 * 33];
    int nc = blockIdx.x, tid = threadIdx.x, lane = tid & 31, tg = tid >> 5;
    int c = nc & 63;
    float m = g_stats[c], r = g_stats[64 + c];
    float sc = r * gm[c], sb = bt[c] - m * sc;
    float a = 0;
    if (lane < 25) {
        size_t base = (size_t)nc * 12800 + lane;
        for (int t = tg; t < 512; t += 8) {
            float y = g_y[base + t * 25];
            float o = fmaxf(y * sc + sb + x[base + t * 25], 0.f);
            g_y2[base + t * 25] = o;
            a += o;
        }
        red[tg * 33 + lane] = a;
    }
    __syncthreads();
    if (tid < 25) {
        float s = 0;
        for (int g = 0; g < 8; g++) s += red[g * 33 + tid];
        g_meanT[nc * 25 + tid] = s * (1.f / 512.f);
    }
}

// ---------------- attention chain ----------------
__global__ void k_sattn(const float* __restrict__ saw, const float* __restrict__ sab) {
    int n = blockIdx.x, v = threadIdx.x;
    if (v < 25) {
        float acc = sab[0];
        for (int c = 0; c < 64; c++) {
            const float* m = &g_meanT[(n * 64 + c) * 25];
            const float* w = &saw[c * 25];
#pragma unroll
            for (int j = 0; j < 25; j++) {
                int vv = v + j - 12;
                if (vv >= 0 && vv < 25) acc += w[j] * m[vv];
            }
        }
        g_gs[n * 25 + v] = 1.f + 1.f / (1.f + expf(-acc));
    }
}

__global__ void __launch_bounds__(256) k_meanV() {
    __shared__ float sgs[25];
    int nc = blockIdx.x, tid = threadIdx.x;
    int n = nc >> 6;
    if (tid < 25) sgs[tid] = g_gs[n * 25 + tid];
    __syncthreads();
    for (int t = tid; t < 512; t += 256) {
        const float* row = &g_y2[(size_t)nc * 12800 + t * 25];
        float a = 0;
#pragma unroll
        for (int v = 0; v < 25; v++) a += row[v] * sgs[v];
        g_meanV[nc * 512 + t] = a * (1.f / 25.f);
    }
}

__global__ void k_tattn(const float* __restrict__ taw, const float* __restrict__ tab) {
    int n = blockIdx.x, tid = threadIdx.x;
    for (int t = tid; t < 512; t += 256) {
        float acc = tab[0];
        for (int c = 0; c < 64; c++) {
            const float* m = &g_meanV[(n * 64 + c) * 512];
            const float* w = &taw[c * 9];
#pragma unroll
            for (int j = 0; j < 9; j++) {
                int tt = t + j - 4;
                if (tt >= 0 && tt < 512) acc += w[j] * m[tt];
            }
        }
        g_gt[n * 512 + t] = 1.f + 1.f / (1.f + expf(-acc));
    }
}

__global__ void k_cse(const float* __restrict__ f1w, const float* __restrict__ f1b,
                      const float* __restrict__ f2w, const float* __restrict__ f2b) {
    __shared__ float sm3[64], sh[32];
    int n = blockIdx.x, c = threadIdx.x;
    const float* m = &g_meanV[(n * 64 + c) * 512];
    const float* gt = &g_gt[n * 512];
    float a = 0;
    for (int t = 0; t < 512; t++) a += m[t] * gt[t];
    sm3[c] = a * (1.f / 512.f);
    __syncthreads();
    if (c < 32) {
        float h = f1b[c];
        for (int k = 0; k < 64; k++) h += f1w[c * 64 + k] * sm3[k];
        sh[c] = fmaxf(h, 0.f);
    }
    __syncthreads();
    float o = f2b[c];
    for (int j = 0; j < 32; j++) o += f2w[c * 32 + j] * sh[j];
    g_gc[n * 64 + c] = 1.f + 1.f / (1.f + expf(-o));
}

// ---------------- TCN via mma.sync bf16-split + BN2 partial epilogue ----------------
#define TCN_SMEM 189440
__global__ void __launch_bounds__(512) k_tcn() {
    extern __shared__ char smemraw[];
    __nv_bfloat16* Ah = (__nv_bfloat16*)smemraw;                 // [408][72]
    __nv_bfloat16* Wh = (__nv_bfloat16*)(smemraw + 117504);      // [64][72]
    __nv_bfloat16* Wl = (__nv_bfloat16*)(smemraw + 126720);
    float* zout = (float*)(smemraw + 135936);                    // [64][209]
    __shared__ float gsg[25], gtg[17], gcg[64];
    int tcb = blockIdx.x, n = blockIdx.y;
    int t0 = tcb * 8, tid = threadIdx.x;
    int wid = tid >> 5, lane = tid & 31;

    if (tid < 25) gsg[tid] = g_gs[n * 25 + tid];
    if (tid >= 32 && tid < 49) {
        int tin = t0 - 4 + (tid - 32);
        gtg[tid - 32] = (tin >= 0 && tin < 512) ? g_gt[n * 512 + tin] : 0.f;
    }
    if (tid >= 64 && tid < 128) gcg[tid - 64] = g_gc[n * 64 + (tid - 64)];
    __syncthreads();

    for (int idx = tid; idx < 408 * 32; idx += 512) {
        int cp = idx / 408, s = idx - cp * 408;
        int tvg = (t0 - 4) * 25 + s;
        float v0 = 0.f, v1 = 0.f;
        if (tvg >= 0 && tvg < 12800) {
            float g = gsg[s % 25] * gtg[s / 25];
            v0 = g_y2[(size_t)(n * 64 + 2 * cp) * 12800 + tvg] * g * gcg[2 * cp];
            v1 = g_y2[(size_t)(n * 64 + 2 * cp + 1) * 12800 + tvg] * g * gcg[2 * cp + 1];
        }
        unsigned uh, ul;
        split2(v0, v1, uh, ul);
        *(unsigned*)&Ah[s * 72 + 2 * cp] = uh;
        *(unsigned*)&Ah[29376 + s * 72 + 2 * cp] = ul;
    }

    int ng = wid & 3, w4 = wid >> 2;
    int nbase = ng * 16;
    int mt[4], cnt = 0;
    for (int m = w4; m < 13; m += 4) mt[cnt++] = m;
    float acc[4][8];
#pragma unroll
    for (int q = 0; q < 4; q++)
#pragma unroll
        for (int i = 0; i < 8; i++) acc[q][i] = 0.f;

    unsigned baseA = su32(Ah), baseW = su32(Wh);
    int arow = lane & 15, acol8 = (lane >> 4) << 3;

    for (int tap = 0; tap < 9; tap++) {
        __syncthreads();
        for (int idx = tid; idx < 4608; idx += 512) {
            Wh[idx] = g_Wt9h[tap * 4608 + idx];
            Wl[idx] = g_Wt9l[tap * 4608 + idx];
        }
        __syncthreads();
#pragma unroll
        for (int ks = 0; ks < 4; ks++) {
            int c0 = ks * 16;
            unsigned bh[4], bl[4];
            unsigned baddr = baseW + (unsigned)(((c0 + arow) * 72 + nbase + acol8) * 2);
            ldsm4t(baddr, bh);
            ldsm4t(baddr + 9216u, bl);
#pragma unroll
            for (int q = 0; q < 4; q++) {
                if (q >= cnt) break;
                int rb = mt[q] * 16 + 25 * tap;
                unsigned aaddr = baseA + (unsigned)(((rb + arow) * 72 + c0 + acol8) * 2);
                unsigned ah[4], al[4];
                ldsm4(aaddr, ah);
                ldsm4(aaddr + 58752u, al);
                mma16816(&acc[q][0], ah, &bh[0]);
                mma16816(&acc[q][0], ah, &bl[0]);
                mma16816(&acc[q][0], al, &bh[0]);
                mma16816(&acc[q][4], ah, &bh[2]);
                mma16816(&acc[q][4], ah, &bl[2]);
                mma16816(&acc[q][4], al, &bh[2]);
            }
        }
    }
    __syncthreads();
#pragma unroll
    for (int q = 0; q < 4; q++) {
        if (q >= cnt) break;
#pragma unroll
        for (int h = 0; h < 2; h++) {
            int o0 = nbase + h * 8 + ((lane & 3) << 1);
            int r0 = mt[q] * 16 + (lane >> 2);
            zout[o0 * 209 + r0] = acc[q][h * 4 + 0];
            zout[(o0 + 1) * 209 + r0] = acc[q][h * 4 + 1];
            zout[o0 * 209 + r0 + 8] = acc[q][h * 4 + 2];
            zout[(o0 + 1) * 209 + r0 + 8] = acc[q][h * 4 + 3];
        }
    }
    __syncthreads();
    for (int idx = tid; idx < 64 * 200; idx += 512) {
        int o = idx / 200, sl = idx - o * 200;
        g_y[((size_t)(n * 64 + o) * 512 + t0) * 25 + sl] = zout[o * 209 + sl];
    }
    float* red = (float*)Wh;
    {
        int o = tid >> 3, sub = tid & 7;
        float a = 0, b = 0;
        for (int sl = sub; sl < 200; sl += 8) {
            float v = zout[o * 209 + sl];
            a += v; b += v * v;
        }
        red[tid] = a; red[512 + tid] = b;
    }
    __syncthreads();
    if (tid < 64) {
        float a = 0, b = 0;
        for (int p = 0; p < 8; p++) { a += red[tid * 8 + p]; b += red[512 + tid * 8 + p]; }
        g_bnS[(size_t)tid * 16384 + n * 64 + tcb] = a;
        g_bnQ[(size_t)tid * 16384 + n * 64 + tcb] = b;
    }
}

// final: out = relu(bn2(g_y) + x), vectorized
__global__ void __launch_bounds__(256) k_bnapply2(
    const float* __restrict__ gm, const float* __restrict__ bt,
    const float* __restrict__ x, float* __restrict__ out)
{
    size_t i4 = (size_t)blockIdx.x * 256 + threadIdx.x;
    size_t flat = i4 * 4;
    int c = (int)((flat / 12800) % 64);
    float m = g_stats[128 + c], r = g_stats[192 + c];
    float sc = r * gm[c];
    float sb = bt[c] - m * sc;
    float4 Y = *(const float4*)&g_y[flat];
    float4 X = *(const float4*)&x[flat];
    float4 O;
    O.x = fmaxf(Y.x * sc + sb + X.x, 0.f);
    O.y = fmaxf(Y.y * sc + sb + X.y, 0.f);
    O.z = fmaxf(Y.z * sc + sb + X.z, 0.f);
    O.w = fmaxf(Y.w * sc + sb + X.w, 0.f);
    *(float4*)&out[flat] = O;
}

// ---------------- launcher ----------------
extern "C" void kernel_launch(void* const* d_in, const int* in_sizes, int n_in,
                              void* d_out, int out_size) {
    const float* x   = (const float*)d_in[0];
    const float* PA  = (const float*)d_in[1];
    const float* alp = (const float*)d_in[2];
    const float* Wa  = (const float*)d_in[3];
    const float* ba  = (const float*)d_in[4];
    const float* Wb  = (const float*)d_in[5];
    const float* bb  = (const float*)d_in[6];
    const float* Wd  = (const float*)d_in[7];
    const float* bng = (const float*)d_in[9];
    const float* bnb = (const float*)d_in[10];
    const float* saw = (const float*)d_in[11];
    const float* sab = (const float*)d_in[12];
    const float* taw = (const float*)d_in[13];
    const float* tab = (const float*)d_in[14];
    const float* f1w = (const float*)d_in[15];
    const float* f1b = (const float*)d_in[16];
    const float* f2w = (const float*)d_in[17];
    const float* f2b = (const float*)d_in[18];
    const float* tw  = (const float*)d_in[19];
    const float* tbg = (const float*)d_in[21];
    const float* tbb = (const float*)d_in[22];
    float* out = (float*)d_out;

    cudaFuncSetAttribute(k_fabgram, cudaFuncAttributeMaxDynamicSharedMemorySize, FAB_SMEM);
    cudaFuncSetAttribute(k_gcn1, cudaFuncAttributeMaxDynamicSharedMemorySize, GCN1_SMEM);
    cudaFuncSetAttribute(k_gcn2, cudaFuncAttributeMaxDynamicSharedMemorySize, GCN2_SMEM);
    cudaFuncSetAttribute(k_tcn, cudaFuncAttributeMaxDynamicSharedMemorySize, TCN_SMEM);

    k_fabgram<<<dim3(64, 8), 256, FAB_SMEM>>>(x, Wa, ba, Wb, bb, Wd, tw);
    k_gram2<<<192, 256>>>(PA, alp);
    k_gcn1<<<dim3(64, 64), 256, GCN1_SMEM>>>(x);
    k_gcn2<<<dim3(100, 64), 512, GCN2_SMEM>>>();
    k_bnfin<<<64, 256>>>(6400, 0);
    k_bnapply_mt<<<4096, 256>>>(bng, bnb, x);
    k_sattn<<<64, 32>>>(saw, sab);
    k_meanV<<<4096, 256>>>();
    k_tattn<<<64, 256>>>(taw, tab);
    k_cse<<<64, 64>>>(f1w, f1b, f2w, f2b);
    k_tcn<<<dim3(64, 64), 512, TCN_SMEM>>>();
    k_bnfin<<<64, 256>>>(4096, 128);
    k_bnapply2<<<51200, 256>>>(tbg, tbb, x, out);
}